// round 1
// baseline (speedup 1.0000x reference)
#include <cuda_runtime.h>
#include <math.h>

#define T 4096
#define E 300
#define HID 512
#define G4 2048          // 4*HID
#define TAGS 12
#define NEGV -10000.0f
#define NB 32            // persistent blocks per direction in LSTM kernel

// ---------------- static device scratch (no allocations allowed) ----------------
__device__ float d_xg[2][T * G4];          // 2 x 32 MB: precomputed input projections
__device__ float d_Hs[2][T * HID];         // 2 x 8 MB : per-step hidden states
__device__ int   d_cnt[2][T];              // per-step arrival counters
__device__ float d_feats[T * TAGS];
__device__ unsigned long long d_bp[T];     // packed backpointers: 12 nibbles per step

// ---------------- reset counters (graph replays reuse state) ----------------
__global__ void init_kernel() {
    int i = blockIdx.x * blockDim.x + threadIdx.x;
    if (i < 2 * T) ((int*)d_cnt)[i] = 0;
}

// ---------------- xg = emb[sentence] @ Wih^T + (bih + bhh) ----------------
// grid (T/32, 2048/256), block 256. Each block: 32 timesteps x 256 rows.
__global__ void __launch_bounds__(256) xg_kernel(
    int dir,
    const int*   __restrict__ sent,
    const float* __restrict__ embt,
    const float* __restrict__ Wih,
    const float* __restrict__ bih,
    const float* __restrict__ bhh)
{
    __shared__ __align__(16) float es[E * 32];   // es[k*32 + t]
    int t0 = blockIdx.x * 32;
    for (int i = threadIdx.x; i < 32 * E; i += 256) {
        int tt = i / E, k = i - tt * E;
        es[k * 32 + tt] = embt[(long long)sent[t0 + tt] * E + k];
    }
    __syncthreads();

    int r = blockIdx.y * 256 + threadIdx.x;
    const float* w = Wih + (long long)r * E;
    float bias = bih[r] + bhh[r];
    float acc[32];
#pragma unroll
    for (int t = 0; t < 32; t++) acc[t] = bias;

    for (int k = 0; k < E; k++) {
        float wv = __ldg(w + k);
        const float4* e4 = (const float4*)(es + k * 32);
#pragma unroll
        for (int q = 0; q < 8; q++) {
            float4 e = e4[q];
            acc[4 * q + 0] += wv * e.x;
            acc[4 * q + 1] += wv * e.y;
            acc[4 * q + 2] += wv * e.z;
            acc[4 * q + 3] += wv * e.w;
        }
    }
    float* xg = d_xg[dir];
#pragma unroll
    for (int t = 0; t < 32; t++)
        xg[(long long)(t0 + t) * G4 + r] = acc[t];
}

// ---------------- persistent BiLSTM recurrence ----------------
// 64 blocks total (32 fwd, 32 bwd), 256 threads each; all co-resident.
// Block b owns 16 hidden indices j in [16b, 16b+16) -> 64 Whh rows
// (rows j, 512+j, 1024+j, 1536+j) held in REGISTERS (128 fp32/thread).
// warp w: col-chunk cc = w>>1 (128 cols), row-group rg = w&1 (32 rows).
// Per step: partial dots -> smem reduce -> activations by tid<16 ->
// global h write -> flag barrier -> reload full h.
__global__ void __launch_bounds__(256, 1) lstm_kernel(
    const float* __restrict__ Whh_f,
    const float* __restrict__ Whh_b)
{
    int bx  = blockIdx.x;
    int dir = bx >> 5;
    int b   = bx & 31;
    const float* Whh = dir ? Whh_b : Whh_f;
    const float* xg  = d_xg[dir];
    float* Hst = d_Hs[dir];
    int*   cnt = d_cnt[dir];

    int tid = threadIdx.x;
    int w = tid >> 5, l = tid & 31;
    int cc = w >> 1;                 // 0..3 column chunk (128 cols each)
    int lr = (w & 1) * 32 + l;       // 0..63 local row
    int grow = ((lr >> 4) << 9) + b * 16 + (lr & 15);  // global gate row

    float wreg[128];
    {
        const float4* wp = (const float4*)(Whh + (long long)grow * HID + cc * 128);
#pragma unroll
        for (int i = 0; i < 32; i++) {
            float4 v = wp[i];
            wreg[4 * i + 0] = v.x; wreg[4 * i + 1] = v.y;
            wreg[4 * i + 2] = v.z; wreg[4 * i + 3] = v.w;
        }
    }

    __shared__ __align__(16) float h_sh[HID];
    __shared__ float part[4][64];

    float c = 0.f;
    float xgv[4] = {0.f, 0.f, 0.f, 0.f};

    h_sh[tid] = 0.f;
    h_sh[tid + 256] = 0.f;
    if (tid < 16) {
        int t0 = dir ? (T - 1) : 0;
#pragma unroll
        for (int g = 0; g < 4; g++)
            xgv[g] = xg[(long long)t0 * G4 + (g << 9) + b * 16 + tid];
    }
    __syncthreads();

    for (int s = 0; s < T; s++) {
        int t = dir ? (T - 1 - s) : s;

        // partial dot: 32 rows x 128 cols per warp, h broadcast from smem
        float a0 = 0.f, a1 = 0.f, a2 = 0.f, a3 = 0.f;
        const float4* h4 = (const float4*)(h_sh + cc * 128);
#pragma unroll
        for (int i = 0; i < 32; i++) {
            float4 hv = h4[i];
            a0 += wreg[4 * i + 0] * hv.x;
            a1 += wreg[4 * i + 1] * hv.y;
            a2 += wreg[4 * i + 2] * hv.z;
            a3 += wreg[4 * i + 3] * hv.w;
        }
        part[cc][lr] = (a0 + a1) + (a2 + a3);
        __syncthreads();

        if (tid < 16) {
            float g0 = part[0][tid]      + part[1][tid]      + part[2][tid]      + part[3][tid]      + xgv[0];
            float g1 = part[0][16 + tid] + part[1][16 + tid] + part[2][16 + tid] + part[3][16 + tid] + xgv[1];
            float g2 = part[0][32 + tid] + part[1][32 + tid] + part[2][32 + tid] + part[3][32 + tid] + xgv[2];
            float g3 = part[0][48 + tid] + part[1][48 + tid] + part[2][48 + tid] + part[3][48 + tid] + xgv[3];
            float ig = 1.f / (1.f + expf(-g0));
            float fg = 1.f / (1.f + expf(-g1));
            float og = 1.f / (1.f + expf(-g3));
            c = fg * c + ig * tanhf(g2);
            float hh = og * tanhf(c);
            Hst[(long long)t * HID + b * 16 + tid] = hh;
        }
        __syncthreads();               // all h-slice stores done block-wide
        if (s == T - 1) break;

        // prefetch next step's xg while we wait on the barrier
        int tn = dir ? (t - 1) : (t + 1);
        if (tid < 16) {
#pragma unroll
            for (int g = 0; g < 4; g++)
                xgv[g] = xg[(long long)tn * G4 + (g << 9) + b * 16 + tid];
        }

        if (tid == 0) {
            __threadfence();
            atomicAdd(&cnt[t], 1);
            volatile int* cv = &cnt[t];
            while (*cv < NB) { }
            __threadfence();
        }
        __syncthreads();

        h_sh[tid]       = __ldcg(Hst + (long long)t * HID + tid);
        h_sh[tid + 256] = __ldcg(Hst + (long long)t * HID + 256 + tid);
        __syncthreads();
    }
}

// ---------------- feats = [h_f, h_b] @ W_out^T + b_out ----------------
// grid 128, block 128, 32 timesteps per block. W_out stays hot in L1/L2.
__global__ void __launch_bounds__(128) feats_kernel(
    const float* __restrict__ W_out,
    const float* __restrict__ b_out)
{
    __shared__ __align__(16) float hb[2 * HID];
    int tid = threadIdx.x;
    int r = tid >> 3, cs = tid & 7;

    for (int tt = 0; tt < 32; tt++) {
        int t = blockIdx.x * 32 + tt;
        __syncthreads();
        ((float4*)hb)[tid]       = ((const float4*)(d_Hs[0] + (long long)t * HID))[tid];
        ((float4*)hb)[128 + tid] = ((const float4*)(d_Hs[1] + (long long)t * HID))[tid];
        __syncthreads();
        if (tid < 96) {
            const float4* wv = (const float4*)(W_out + r * 1024 + cs * 128);
            const float4* hv = (const float4*)(hb + cs * 128);
            float s0 = 0.f, s1 = 0.f, s2 = 0.f, s3 = 0.f;
#pragma unroll
            for (int i = 0; i < 32; i++) {
                float4 a = __ldg(wv + i);
                float4 bq = hv[i];
                s0 += a.x * bq.x; s1 += a.y * bq.y;
                s2 += a.z * bq.z; s3 += a.w * bq.w;
            }
            float sum = (s0 + s1) + (s2 + s3);
#pragma unroll
            for (int o = 4; o >= 1; o >>= 1)
                sum += __shfl_down_sync(0xffffffffu, sum, o);
            if (cs == 0)
                d_feats[t * TAGS + r] = sum + b_out[r];
        }
    }
}

// ---------------- Viterbi: forward scan + packed backtrace ----------------
// One warp. fv[tag] lives in lane tag. Strict-> scan == jnp.argmax first-tie.
__global__ void viterbi_kernel(const float* __restrict__ trans,
                               float* __restrict__ out)
{
    __shared__ unsigned long long bps[T];
    int l = threadIdx.x;

    float tr[TAGS];
    if (l < TAGS) {
#pragma unroll
        for (int p = 0; p < TAGS; p++) tr[p] = trans[l * TAGS + p];
    } else {
#pragma unroll
        for (int p = 0; p < TAGS; p++) tr[p] = 0.f;
    }

    float fv = (l == 10) ? 0.f : NEGV;   // START = 10
    float featnext = (l < TAGS) ? d_feats[l] : 0.f;

    for (int t = 0; t < T; t++) {
        float feat = featnext;
        if (t + 1 < T && l < TAGS) featnext = d_feats[(t + 1) * TAGS + l];

        float m = -3.4e38f; int am = 0;
#pragma unroll
        for (int p = 0; p < TAGS; p++) {
            float v = __shfl_sync(0xffffffffu, fv, p) + tr[p];
            if (v > m) { m = v; am = p; }
        }
        unsigned lo = (l < 8)              ? ((unsigned)am << (4 * l))       : 0u;
        unsigned hi = (l >= 8 && l < TAGS) ? ((unsigned)am << (4 * (l - 8))) : 0u;
        lo = __reduce_add_sync(0xffffffffu, lo);
        hi = __reduce_add_sync(0xffffffffu, hi);
        if (l == 0) d_bp[t] = ((unsigned long long)hi << 32) | lo;

        fv = m + feat;
    }

    // termination: term = fv + transitions[STOP]; term[STOP]=term[START]=NEG
    float term;
    if (l < TAGS) term = fv + trans[11 * TAGS + l];
    else          term = -3.4e38f;
    if (l == 11 || l == 10) term = NEGV;

    int best = 0; float sc = -3.4e38f;
#pragma unroll
    for (int p = 0; p < TAGS; p++) {
        float v = __shfl_sync(0xffffffffu, term, p);
        if (v > sc) { sc = v; best = p; }
    }

    for (int i = l; i < T; i += 32) bps[i] = d_bp[i];
    __syncwarp();

    if (l == 0) {
        out[0] = sc;
        out[T] = (float)best;            // path[T-1]
        int tag = best;
        for (int t = T - 1; t >= 1; t--) {
            int prev = (int)((bps[t] >> (4 * tag)) & 15ull);
            out[t] = (float)prev;        // path[t-1] = chain[t]
            tag = prev;
        }
    }
}

// ---------------- launch ----------------
extern "C" void kernel_launch(void* const* d_in, const int* in_sizes, int n_in,
                              void* d_out, int out_size)
{
    const int*   sent  = (const int*)d_in[0];
    const float* embt  = (const float*)d_in[1];
    const float* Wih_f = (const float*)d_in[2];
    const float* Whh_f = (const float*)d_in[3];
    const float* bih_f = (const float*)d_in[4];
    const float* bhh_f = (const float*)d_in[5];
    const float* Wih_b = (const float*)d_in[6];
    const float* Whh_b = (const float*)d_in[7];
    const float* bih_b = (const float*)d_in[8];
    const float* bhh_b = (const float*)d_in[9];
    const float* W_out = (const float*)d_in[10];
    const float* b_out = (const float*)d_in[11];
    const float* trans = (const float*)d_in[12];
    float* out = (float*)d_out;

    init_kernel<<<8, 1024>>>();
    dim3 g(T / 32, G4 / 256);
    xg_kernel<<<g, 256>>>(0, sent, embt, Wih_f, bih_f, bhh_f);
    xg_kernel<<<g, 256>>>(1, sent, embt, Wih_b, bih_b, bhh_b);
    lstm_kernel<<<2 * NB, 256>>>(Whh_f, Whh_b);
    feats_kernel<<<128, 128>>>(W_out, b_out);
    viterbi_kernel<<<1, 32>>>(trans, out);
}